// round 11
// baseline (speedup 1.0000x reference)
#include <cuda_runtime.h>
#include <math.h>

// features: [B=16, H=128, W=128, D=8, F=16] float32
// out[b,h,w,d,f] = flip_{W,D}( roll_{(5,-7),(H,W)}( rotate_40deg_NN(x) ) )
//
// Inverse chain per output element:
//   w1 = W-1-w ; d1 = D-1-d                    (undo flips)
//   h2 = (h-5) mod H ; w2 = (w1+7) mod W       (undo roll)
//   (si,sj,valid) = NN inverse-rotation at (h2,w2)
//   out = valid ? x[b, si, sj, d1, f] : 0
//
// R9: 256-bit accesses, unroll x4 across batches.
//   loads : ld.global.nc.v8.b32 (plain — hints proven useless in R5/R8)
//   stores: st.global.wt.v8.b32 (write-through: output stream should not
//           allocate dirty L2 lines, letting the input stay L2-resident
//           across graph replays and killing the ~35MB/replay read misses)

#define B_ 16
#define H_ 128
#define W_ 128
#define D_ 8
#define F8_ 2                     // F/8
#define N8_ (B_*H_*W_*D_*F8_)     // 4194304 8-float outputs
#define UNROLL_ 4
#define STRIDE_ (N8_/UNROLL_)     // 1048576 = 4 batches
#define BATCH8_ (H_*W_*D_*F8_)    // 8-float groups per batch = 262144

struct f8vec { unsigned r0,r1,r2,r3,r4,r5,r6,r7; };

__device__ __forceinline__ f8vec ldg_v8(const unsigned* p) {
    f8vec v;
    asm volatile("ld.global.nc.v8.b32 {%0,%1,%2,%3,%4,%5,%6,%7}, [%8];"
                 : "=r"(v.r0), "=r"(v.r1), "=r"(v.r2), "=r"(v.r3),
                   "=r"(v.r4), "=r"(v.r5), "=r"(v.r6), "=r"(v.r7)
                 : "l"(p));
    return v;
}

__device__ __forceinline__ void stg_v8_wt(unsigned* p, const f8vec& v) {
    asm volatile("st.global.wt.v8.b32 [%0], {%1,%2,%3,%4,%5,%6,%7,%8};"
                 :: "l"(p),
                    "r"(v.r0), "r"(v.r1), "r"(v.r2), "r"(v.r3),
                    "r"(v.r4), "r"(v.r5), "r"(v.r6), "r"(v.r7)
                 : "memory");
}

__global__ __launch_bounds__(256) void augment_kernel(
    const unsigned* __restrict__ in, unsigned* __restrict__ out,
    float c, float s)
{
    int idx = blockIdx.x * blockDim.x + threadIdx.x;   // 0 .. STRIDE_-1

    // decompose: idx = (((b*H + h)*W + w)*D + d)*F8 + f8   (b in 0..3 here)
    int f8 = idx & 1;
    int t  = idx >> 1;
    int d  = t & 7;   t >>= 3;
    int w  = t & 127; t >>= 7;
    int h  = t & 127;
    int b  = t >> 7;

    // undo flips
    int w1 = (W_ - 1) - w;
    int d1 = (D_ - 1) - d;
    // undo roll (shifts = (5, -7) on (H, W))
    int h2 = h - 5;  if (h2 < 0)    h2 += H_;
    int w2 = w1 + 7; if (w2 >= W_)  w2 -= W_;

    // NN inverse rotation, center 63.5, round-half-to-even (jnp.round)
    float fi = (float)h2 - 63.5f;
    float fj = (float)w2 - 63.5f;
    float src_i =  c * fi + s * fj + 63.5f;
    float src_j = -s * fi + c * fj + 63.5f;
    int si = (int)rintf(src_i);
    int sj = (int)rintf(src_j);

    bool valid = (si >= 0) & (si < H_) & (sj >= 0) & (sj < W_);

    f8vec v[UNROLL_];
    if (valid) {
        int src = ((((b * H_ + si) * W_ + sj) * D_ + d1) * F8_ + f8) * 8;
        #pragma unroll
        for (int k = 0; k < UNROLL_; k++)
            v[k] = ldg_v8(&in[src + k * (4 * BATCH8_ * 8)]);
    } else {
        #pragma unroll
        for (int k = 0; k < UNROLL_; k++)
            v[k] = f8vec{0,0,0,0,0,0,0,0};
    }

    #pragma unroll
    for (int k = 0; k < UNROLL_; k++)
        stg_v8_wt(&out[(idx + k * STRIDE_) * 8], v[k]);
}

extern "C" void kernel_launch(void* const* d_in, const int* in_sizes, int n_in,
                              void* d_out, int out_size) {
    const unsigned* in = (const unsigned*)d_in[0];
    unsigned* out = (unsigned*)d_out;

    const double theta = 40.0 * 3.14159265358979323846 / 180.0;
    const float c = (float)cos(theta);
    const float s = (float)sin(theta);

    const int threads = 256;
    const int blocks = STRIDE_ / threads;   // 4096
    augment_kernel<<<blocks, threads>>>(in, out, c, s);
}